// round 9
// baseline (speedup 1.0000x reference)
#include <cuda_runtime.h>
#include <math.h>

// Problem constants (fixed by setup_inputs): bs=16, C=256, H=W=128
#define BS 16
#define CC 256
#define NN 16384           // H*W
#define TOPK 12

typedef unsigned long long ull;

// ---------------- scratch (device globals; no allocation allowed) ----------
__device__ __align__(16) float g_fmask_fg[BS][NN];   // 1 MB: fg mask as 0.0/1.0
__device__ __align__(16) float g_fmask_bg[BS][NN];   // 1 MB: bg mask as 0.0/1.0
__device__ int   g_cnt[2][BS];
__device__ int   g_flagbad[BS];                      // !=0 if fg/bg not exact complements
__device__ float g_fallback[2][BS][CC];              // topk means (written only if cnt==0)

// ---------------- packed f32x2 helpers (ptxas won't auto-fuse) -------------
__device__ __forceinline__ ull add2(ull a, ull b) {
    ull d; asm("add.rn.f32x2 %0, %1, %2;" : "=l"(d) : "l"(a), "l"(b)); return d;
}
__device__ __forceinline__ ull fma2(ull a, ull b, ull c) {
    ull d; asm("fma.rn.f32x2 %0, %1, %2, %3;" : "=l"(d) : "l"(a), "l"(b), "l"(c)); return d;
}
__device__ __forceinline__ float up_sum(ull v) {
    float x, y; asm("mov.b64 {%0, %1}, %2;" : "=f"(x), "=f"(y) : "l"(v)); return x + y;
}

// ---------------------------------------------------------------------------
// Kernel 1: softmax -> float masks (0.0/1.0), counts, complement flag.
// grid = 16 (one block per b), block = 256
// ---------------------------------------------------------------------------
__global__ void __launch_bounds__(256) mask_kernel(const float* __restrict__ outp,
                                                   const float* __restrict__ tau_p) {
    const int b = blockIdx.x;
    const int t = threadIdx.x;

    const float tau = *tau_p;
    const float Tf  = 1.0f / (1.0f + expf(-tau));   // sigmoid(tau)
    const float Tb  = 1.0f - Tf;

    const float* o0 = outp + (size_t)b * (2 * NN);
    const float* o1 = o0 + NN;

    int cf = 0, cb = 0;
    bool bad = false;
    #pragma unroll 4
    for (int i = 0; i < 64; i++) {
        const int n = i * 256 + t;
        const float a  = o0[n];
        const float b1 = o1[n];
        const float m  = fmaxf(a, b1);
        const float e0 = expf(a - m);
        const float e1 = expf(b1 - m);
        const float s  = e0 + e1;
        const float pf = e1 / s;                    // softmax channel 1 (fg)
        const float pb = e0 / s;                    // softmax channel 0 (bg)
        const bool ff = pf > Tf;
        const bool fb = pb > Tb;
        g_fmask_fg[b][n] = ff ? 1.0f : 0.0f;
        g_fmask_bg[b][n] = fb ? 1.0f : 0.0f;
        cf += ff; cb += fb;
        bad |= (ff == fb);                           // not exact complements
    }

    // block reduce
    #pragma unroll
    for (int o = 16; o > 0; o >>= 1) {
        cf += __shfl_down_sync(0xffffffffu, cf, o);
        cb += __shfl_down_sync(0xffffffffu, cb, o);
    }
    const int anybad = __any_sync(0xffffffffu, bad) ? 1 : 0;

    __shared__ int rf[8], rb[8], rbad[8];
    const int w = t >> 5, l = t & 31;
    if (l == 0) { rf[w] = cf; rb[w] = cb; rbad[w] = anybad; }
    __syncthreads();
    if (t == 0) {
        int a = 0, c = 0, d = 0;
        #pragma unroll
        for (int i = 0; i < 8; i++) { a += rf[i]; c += rb[i]; d += rbad[i]; }
        g_cnt[0][b]  = a;
        g_cnt[1][b]  = c;
        g_flagbad[b] = d;
    }
}

// ---------------------------------------------------------------------------
// Kernel 2: exact top-12 of pred per (b, side); then gather fallback means
// for all 256 channels. Early-exits (cnt>0) in the hot case.
// grid = (16, 2), block = 256
// ---------------------------------------------------------------------------
__global__ void __launch_bounds__(256) topk_kernel(const float* __restrict__ outp,
                                                   const float* __restrict__ feat) {
    const int b    = blockIdx.x;
    const int side = blockIdx.y;
    if (g_cnt[side][b] > 0) return;   // uniform early exit (hot case)

    const int t = threadIdx.x;
    const float* o0 = outp + (size_t)b * (2 * NN);
    const float* o1 = o0 + NN;

    float v[TOPK];
    int   ix[TOPK];
    #pragma unroll
    for (int k = 0; k < TOPK; k++) { v[k] = -INFINITY; ix[k] = 0x7fffffff; }

    for (int j = t; j < NN; j += 256) {
        const float a  = o0[j];
        const float b1 = o1[j];
        const float m  = fmaxf(a, b1);
        const float e0 = expf(a - m);
        const float e1 = expf(b1 - m);
        const float s  = e0 + e1;
        const float p  = (side == 0) ? (e1 / s) : (e0 / s);
        if ((p > v[TOPK - 1]) || (p == v[TOPK - 1] && j < ix[TOPK - 1])) {
            int k = TOPK - 1;
            while (k > 0 && ((p > v[k - 1]) || (p == v[k - 1] && j < ix[k - 1]))) {
                v[k] = v[k - 1]; ix[k] = ix[k - 1]; k--;
            }
            v[k] = p; ix[k] = j;
        }
    }

    __shared__ float sv[256 * TOPK];
    __shared__ int   si[256 * TOPK];
    #pragma unroll
    for (int k = 0; k < TOPK; k++) { sv[t * TOPK + k] = v[k]; si[t * TOPK + k] = ix[k]; }
    __syncthreads();

    for (int stride = 128; stride > 0; stride >>= 1) {
        if (t < stride) {
            float* A  = &sv[t * TOPK];
            int*   Ai = &si[t * TOPK];
            float* B  = &sv[(t + stride) * TOPK];
            int*   Bi = &si[(t + stride) * TOPK];
            float mv[TOPK]; int mi[TOPK];
            int i = 0, j = 0;
            #pragma unroll
            for (int o = 0; o < TOPK; o++) {
                const float av = A[i], bv = B[j];
                const int aix = Ai[i], bix = Bi[j];
                const bool takeA = (av > bv) || (av == bv && aix <= bix);
                if (takeA) { mv[o] = av; mi[o] = aix; i++; }
                else       { mv[o] = bv; mi[o] = bix; j++; }
            }
            #pragma unroll
            for (int o = 0; o < TOPK; o++) { A[o] = mv[o]; Ai[o] = mi[o]; }
        }
        __syncthreads();
    }

    // Gather fallback means for all 256 channels (thread t = channel t)
    const float* rowc = feat + (((size_t)b * CC + t) << 14);
    float s = 0.0f;
    #pragma unroll
    for (int k = 0; k < TOPK; k++) s += rowc[si[k]];
    g_fallback[side][b][t] = s * (1.0f / 12.0f);
}

// ---------------------------------------------------------------------------
// Kernel 3: the 268 MB streaming pass + output write.
// grid = (32, 16): cg = blockIdx.x, b = blockIdx.y. block = 256 (8 warps).
// Warp w owns channel c = cg*8 + w entirely (full 16384-element row) ->
// reduction only once per row. fg-mask floats staged in 32 KB smem half-tiles,
// shared by all 8 warps. Inner loop: LDG.128 + LDS.128 + 2 ADD.f32x2 +
// 2 FFMA.f32x2 = 6 inst / 16 bytes -> memory-bound.
// ---------------------------------------------------------------------------
__global__ void __launch_bounds__(256) sum_kernel(const float* __restrict__ feat,
                                                  float* __restrict__ outp) {
    __shared__ __align__(16) float s_m[8192];   // 32 KB: half of one mask row

    const int t    = threadIdx.x;
    const int w    = t >> 5;
    const int lane = t & 31;
    const int cg   = blockIdx.x;
    const int b    = blockIdx.y;
    const int c    = cg * 8 + w;

    const bool bad = (g_flagbad[b] != 0);

    const longlong2* rowv = (const longlong2*)(feat + (((size_t)b * CC + c) << 14));
    const longlong2* bgmv = (const longlong2*)(&g_fmask_bg[b][0]);

    ull t2a = 0ull, t2b = 0ull;   // packed running totals
    ull f2a = 0ull, f2b = 0ull;   // packed fg sums
    ull g2a = 0ull, g2b = 0ull;   // packed bg sums (bad path only)

    for (int h = 0; h < 2; h++) {
        // stage half of the fg float-mask row into smem (all 256 threads)
        const float4* src = (const float4*)(&g_fmask_fg[b][h * 8192]);
        float4*       dst = (float4*)s_m;
        #pragma unroll
        for (int j = 0; j < 8; j++) dst[j * 256 + t] = src[j * 256 + t];
        __syncthreads();

        const longlong2* smv = (const longlong2*)s_m;
        const longlong2* rv  = rowv + h * 2048;
        const longlong2* bv  = bgmv + h * 2048;

        if (!bad) {
            #pragma unroll 8
            for (int it = 0; it < 64; it++) {
                const longlong2 f = rv[it * 32 + lane];
                const longlong2 m = smv[it * 32 + lane];
                if (it & 1) {
                    t2b = add2(t2b, add2((ull)f.x, (ull)f.y));
                    f2b = fma2((ull)f.x, (ull)m.x, f2b);
                    f2b = fma2((ull)f.y, (ull)m.y, f2b);
                } else {
                    t2a = add2(t2a, add2((ull)f.x, (ull)f.y));
                    f2a = fma2((ull)f.x, (ull)m.x, f2a);
                    f2a = fma2((ull)f.y, (ull)m.y, f2a);
                }
            }
        } else {
            #pragma unroll 4
            for (int it = 0; it < 64; it++) {
                const longlong2 f  = rv[it * 32 + lane];
                const longlong2 m  = smv[it * 32 + lane];
                const longlong2 mb = bv[it * 32 + lane];
                if (it & 1) {
                    f2b = fma2((ull)f.x, (ull)m.x,  f2b);
                    f2b = fma2((ull)f.y, (ull)m.y,  f2b);
                    g2b = fma2((ull)f.x, (ull)mb.x, g2b);
                    g2b = fma2((ull)f.y, (ull)mb.y, g2b);
                } else {
                    f2a = fma2((ull)f.x, (ull)m.x,  f2a);
                    f2a = fma2((ull)f.y, (ull)m.y,  f2a);
                    g2a = fma2((ull)f.x, (ull)mb.x, g2a);
                    g2a = fma2((ull)f.y, (ull)mb.y, g2a);
                }
            }
        }
        __syncthreads();   // before next stage overwrites s_m
    }

    // unpack + warp reduce (one row per warp -> amortized)
    float tot = up_sum(t2a) + up_sum(t2b);
    float fg  = up_sum(f2a) + up_sum(f2b);
    float bg  = up_sum(g2a) + up_sum(g2b);
    #pragma unroll
    for (int o = 16; o > 0; o >>= 1) {
        tot += __shfl_down_sync(0xffffffffu, tot, o);
        fg  += __shfl_down_sync(0xffffffffu, fg,  o);
        bg  += __shfl_down_sync(0xffffffffu, bg,  o);
    }

    if (lane == 0) {
        const float bgs = bad ? bg : (tot - fg);
        const int cf = g_cnt[0][b];
        const int cb = g_cnt[1][b];
        const float vf = (cf > 0) ? fg  / (float)cf : g_fallback[0][b][c];
        const float vb = (cb > 0) ? bgs / (float)cb : g_fallback[1][b][c];
        outp[b * CC + c]        = vf;   // fg_proto
        outp[4096 + b * CC + c] = vb;   // bg_proto
    }
}

// ---------------------------------------------------------------------------
extern "C" void kernel_launch(void* const* d_in, const int* in_sizes, int n_in,
                              void* d_out, int out_size) {
    (void)in_sizes; (void)n_in; (void)out_size;
    const float* feat = (const float*)d_in[0];   // (16,256,128,128) f32
    const float* outv = (const float*)d_in[1];   // (16,2,128,128)   f32
    const float* tau  = (const float*)d_in[2];   // scalar f32
    float* outp = (float*)d_out;                 // 8192 f32: fg(4096) ++ bg(4096)

    mask_kernel<<<BS, 256>>>(outv, tau);
    topk_kernel<<<dim3(BS, 2), 256>>>(outv, feat);
    sum_kernel<<<dim3(32, BS), 256>>>(feat, outp);
}

// round 10
// speedup vs baseline: 1.5877x; 1.5877x over previous
#include <cuda_runtime.h>
#include <math.h>

// Problem constants (fixed by setup_inputs): bs=16, C=256, H=W=128
#define BS 16
#define CC 256
#define NN 16384           // H*W
#define TOPK 12
#define MCHUNKS 16         // mask kernel chunks per batch

typedef unsigned long long ull;

// ---------------- scratch (device globals; no allocation allowed) ----------
__device__ __align__(16) float g_fmask_fg[BS][NN];   // 1 MB: fg mask as 0.0/1.0
__device__ __align__(16) float g_fmask_bg[BS][NN];   // 1 MB: bg mask as 0.0/1.0
__device__ int   g_part_cf[BS][MCHUNKS];
__device__ int   g_part_cb[BS][MCHUNKS];
__device__ int   g_part_bad[BS][MCHUNKS];
__device__ int   g_cnt[2][BS];
__device__ int   g_flagbad[BS];                      // !=0 if fg/bg not exact complements
__device__ float g_fallback[2][BS][CC];              // topk means (written only if cnt==0)

// ---------------- packed f32x2 helpers (ptxas won't auto-fuse) -------------
__device__ __forceinline__ ull add2(ull a, ull b) {
    ull d; asm("add.rn.f32x2 %0, %1, %2;" : "=l"(d) : "l"(a), "l"(b)); return d;
}
__device__ __forceinline__ ull fma2(ull a, ull b, ull c) {
    ull d; asm("fma.rn.f32x2 %0, %1, %2, %3;" : "=l"(d) : "l"(a), "l"(b), "l"(c)); return d;
}
__device__ __forceinline__ float up_sum(ull v) {
    float x, y; asm("mov.b64 {%0, %1}, %2;" : "=f"(x), "=f"(y) : "l"(v)); return x + y;
}

// ---------------------------------------------------------------------------
// Kernel 1: softmax -> float masks (0.0/1.0), per-block partial counts.
// grid = (16, 16) = 256 blocks (full chip), block = 256, one float4/thread.
// ---------------------------------------------------------------------------
__global__ void __launch_bounds__(256) mask_kernel(const float* __restrict__ outp,
                                                   const float* __restrict__ tau_p) {
    const int b  = blockIdx.x;
    const int ch = blockIdx.y;
    const int t  = threadIdx.x;

    const float tau = *tau_p;
    const float Tf  = 1.0f / (1.0f + expf(-tau));   // sigmoid(tau)
    const float Tb  = 1.0f - Tf;

    const int base = ch * 1024;                     // 1024 elements per block
    const float4* o0 = (const float4*)(outp + (size_t)b * (2 * NN) + base);
    const float4* o1 = (const float4*)(outp + (size_t)b * (2 * NN) + NN + base);

    const float4 a  = o0[t];
    const float4 b1 = o1[t];

    float4 mf, mb;
    int cf = 0, cb = 0, bad = 0;
    {
        const float av[4] = {a.x, a.y, a.z, a.w};
        const float bv[4] = {b1.x, b1.y, b1.z, b1.w};
        float rf[4], rb[4];
        #pragma unroll
        for (int k = 0; k < 4; k++) {
            const float m  = fmaxf(av[k], bv[k]);
            const float e0 = expf(av[k] - m);
            const float e1 = expf(bv[k] - m);
            const float s  = e0 + e1;
            const float pf = e1 / s;                // softmax channel 1 (fg)
            const float pb = e0 / s;                // softmax channel 0 (bg)
            const bool ff = pf > Tf;
            const bool fb = pb > Tb;
            rf[k] = ff ? 1.0f : 0.0f;
            rb[k] = fb ? 1.0f : 0.0f;
            cf += ff; cb += fb;
            bad += (ff == fb);
        }
        mf.x = rf[0]; mf.y = rf[1]; mf.z = rf[2]; mf.w = rf[3];
        mb.x = rb[0]; mb.y = rb[1]; mb.z = rb[2]; mb.w = rb[3];
    }
    ((float4*)(&g_fmask_fg[b][base]))[t] = mf;
    ((float4*)(&g_fmask_bg[b][base]))[t] = mb;

    // block reduce partial counts
    #pragma unroll
    for (int o = 16; o > 0; o >>= 1) {
        cf  += __shfl_down_sync(0xffffffffu, cf,  o);
        cb  += __shfl_down_sync(0xffffffffu, cb,  o);
        bad += __shfl_down_sync(0xffffffffu, bad, o);
    }
    __shared__ int rf8[8], rb8[8], rd8[8];
    const int w = t >> 5, l = t & 31;
    if (l == 0) { rf8[w] = cf; rb8[w] = cb; rd8[w] = bad; }
    __syncthreads();
    if (t == 0) {
        int A = 0, B2 = 0, D = 0;
        #pragma unroll
        for (int i = 0; i < 8; i++) { A += rf8[i]; B2 += rb8[i]; D += rd8[i]; }
        g_part_cf[b][ch]  = A;
        g_part_cb[b][ch]  = B2;
        g_part_bad[b][ch] = D;
    }
}

// ---------------------------------------------------------------------------
// Kernel 1b: fold partials -> g_cnt / g_flagbad. 1 block, 48 threads used.
// ---------------------------------------------------------------------------
__global__ void __launch_bounds__(64) reduce_kernel() {
    const int t = threadIdx.x;
    if (t < BS) {
        int s = 0;
        #pragma unroll
        for (int i = 0; i < MCHUNKS; i++) s += g_part_cf[t][i];
        g_cnt[0][t] = s;
    } else if (t < 2 * BS) {
        const int b = t - BS;
        int s = 0;
        #pragma unroll
        for (int i = 0; i < MCHUNKS; i++) s += g_part_cb[b][i];
        g_cnt[1][b] = s;
    } else if (t < 3 * BS) {
        const int b = t - 2 * BS;
        int s = 0;
        #pragma unroll
        for (int i = 0; i < MCHUNKS; i++) s += g_part_bad[b][i];
        g_flagbad[b] = s;
    }
}

// ---------------------------------------------------------------------------
// Kernel 2: exact top-12 of pred per (b, side); then gather fallback means
// for all 256 channels. Early-exits (cnt>0) in the hot case.
// grid = (16, 2), block = 256
// ---------------------------------------------------------------------------
__global__ void __launch_bounds__(256) topk_kernel(const float* __restrict__ outp,
                                                   const float* __restrict__ feat) {
    const int b    = blockIdx.x;
    const int side = blockIdx.y;
    if (g_cnt[side][b] > 0) return;   // uniform early exit (hot case)

    const int t = threadIdx.x;
    const float* o0 = outp + (size_t)b * (2 * NN);
    const float* o1 = o0 + NN;

    float v[TOPK];
    int   ix[TOPK];
    #pragma unroll
    for (int k = 0; k < TOPK; k++) { v[k] = -INFINITY; ix[k] = 0x7fffffff; }

    for (int j = t; j < NN; j += 256) {
        const float a  = o0[j];
        const float b1 = o1[j];
        const float m  = fmaxf(a, b1);
        const float e0 = expf(a - m);
        const float e1 = expf(b1 - m);
        const float s  = e0 + e1;
        const float p  = (side == 0) ? (e1 / s) : (e0 / s);
        if ((p > v[TOPK - 1]) || (p == v[TOPK - 1] && j < ix[TOPK - 1])) {
            int k = TOPK - 1;
            while (k > 0 && ((p > v[k - 1]) || (p == v[k - 1] && j < ix[k - 1]))) {
                v[k] = v[k - 1]; ix[k] = ix[k - 1]; k--;
            }
            v[k] = p; ix[k] = j;
        }
    }

    __shared__ float sv[256 * TOPK];
    __shared__ int   si[256 * TOPK];
    #pragma unroll
    for (int k = 0; k < TOPK; k++) { sv[t * TOPK + k] = v[k]; si[t * TOPK + k] = ix[k]; }
    __syncthreads();

    for (int stride = 128; stride > 0; stride >>= 1) {
        if (t < stride) {
            float* A  = &sv[t * TOPK];
            int*   Ai = &si[t * TOPK];
            float* B  = &sv[(t + stride) * TOPK];
            int*   Bi = &si[(t + stride) * TOPK];
            float mv[TOPK]; int mi[TOPK];
            int i = 0, j = 0;
            #pragma unroll
            for (int o = 0; o < TOPK; o++) {
                const float av = A[i], bv = B[j];
                const int aix = Ai[i], bix = Bi[j];
                const bool takeA = (av > bv) || (av == bv && aix <= bix);
                if (takeA) { mv[o] = av; mi[o] = aix; i++; }
                else       { mv[o] = bv; mi[o] = bix; j++; }
            }
            #pragma unroll
            for (int o = 0; o < TOPK; o++) { A[o] = mv[o]; Ai[o] = mi[o]; }
        }
        __syncthreads();
    }

    // Gather fallback means for all 256 channels (thread t = channel t)
    const float* rowc = feat + (((size_t)b * CC + t) << 14);
    float s = 0.0f;
    #pragma unroll
    for (int k = 0; k < TOPK; k++) s += rowc[si[k]];
    g_fallback[side][b][t] = s * (1.0f / 12.0f);
}

// ---------------------------------------------------------------------------
// Kernel 3: the 268 MB streaming pass + output write. (validated in R8)
// grid = (32, 16): cg = blockIdx.x, b = blockIdx.y. block = 256 (8 warps).
// Warp w owns channel c = cg*8 + w entirely. fg-mask floats staged in 32 KB
// smem half-tiles. Inner loop: LDG.128 + LDS.128 + 2 ADD.f32x2 + 2 FFMA.f32x2
// = 6 inst / 16 bytes -> memory-bound.
// ---------------------------------------------------------------------------
__global__ void __launch_bounds__(256) sum_kernel(const float* __restrict__ feat,
                                                  float* __restrict__ outp) {
    __shared__ __align__(16) float s_m[8192];   // 32 KB: half of one mask row

    const int t    = threadIdx.x;
    const int w    = t >> 5;
    const int lane = t & 31;
    const int cg   = blockIdx.x;
    const int b    = blockIdx.y;
    const int c    = cg * 8 + w;

    const bool bad = (g_flagbad[b] != 0);

    const longlong2* rowv = (const longlong2*)(feat + (((size_t)b * CC + c) << 14));
    const longlong2* bgmv = (const longlong2*)(&g_fmask_bg[b][0]);

    ull t2a = 0ull, t2b = 0ull;   // packed running totals
    ull f2a = 0ull, f2b = 0ull;   // packed fg sums
    ull g2a = 0ull, g2b = 0ull;   // packed bg sums (bad path only)

    for (int h = 0; h < 2; h++) {
        // stage half of the fg float-mask row into smem (all 256 threads)
        const float4* src = (const float4*)(&g_fmask_fg[b][h * 8192]);
        float4*       dst = (float4*)s_m;
        #pragma unroll
        for (int j = 0; j < 8; j++) dst[j * 256 + t] = src[j * 256 + t];
        __syncthreads();

        const longlong2* smv = (const longlong2*)s_m;
        const longlong2* rv  = rowv + h * 2048;
        const longlong2* bv  = bgmv + h * 2048;

        if (!bad) {
            #pragma unroll 8
            for (int it = 0; it < 64; it++) {
                const longlong2 f = rv[it * 32 + lane];
                const longlong2 m = smv[it * 32 + lane];
                if (it & 1) {
                    t2b = add2(t2b, add2((ull)f.x, (ull)f.y));
                    f2b = fma2((ull)f.x, (ull)m.x, f2b);
                    f2b = fma2((ull)f.y, (ull)m.y, f2b);
                } else {
                    t2a = add2(t2a, add2((ull)f.x, (ull)f.y));
                    f2a = fma2((ull)f.x, (ull)m.x, f2a);
                    f2a = fma2((ull)f.y, (ull)m.y, f2a);
                }
            }
        } else {
            #pragma unroll 4
            for (int it = 0; it < 64; it++) {
                const longlong2 f  = rv[it * 32 + lane];
                const longlong2 m  = smv[it * 32 + lane];
                const longlong2 mb = bv[it * 32 + lane];
                if (it & 1) {
                    f2b = fma2((ull)f.x, (ull)m.x,  f2b);
                    f2b = fma2((ull)f.y, (ull)m.y,  f2b);
                    g2b = fma2((ull)f.x, (ull)mb.x, g2b);
                    g2b = fma2((ull)f.y, (ull)mb.y, g2b);
                } else {
                    f2a = fma2((ull)f.x, (ull)m.x,  f2a);
                    f2a = fma2((ull)f.y, (ull)m.y,  f2a);
                    g2a = fma2((ull)f.x, (ull)mb.x, g2a);
                    g2a = fma2((ull)f.y, (ull)mb.y, g2a);
                }
            }
        }
        __syncthreads();   // before next stage overwrites s_m
    }

    // unpack + warp reduce (one row per warp -> amortized)
    float tot = up_sum(t2a) + up_sum(t2b);
    float fg  = up_sum(f2a) + up_sum(f2b);
    float bg  = up_sum(g2a) + up_sum(g2b);
    #pragma unroll
    for (int o = 16; o > 0; o >>= 1) {
        tot += __shfl_down_sync(0xffffffffu, tot, o);
        fg  += __shfl_down_sync(0xffffffffu, fg,  o);
        bg  += __shfl_down_sync(0xffffffffu, bg,  o);
    }

    if (lane == 0) {
        const float bgs = bad ? bg : (tot - fg);
        const int cf = g_cnt[0][b];
        const int cb = g_cnt[1][b];
        const float vf = (cf > 0) ? fg  / (float)cf : g_fallback[0][b][c];
        const float vb = (cb > 0) ? bgs / (float)cb : g_fallback[1][b][c];
        outp[b * CC + c]        = vf;   // fg_proto
        outp[4096 + b * CC + c] = vb;   // bg_proto
    }
}

// ---------------------------------------------------------------------------
extern "C" void kernel_launch(void* const* d_in, const int* in_sizes, int n_in,
                              void* d_out, int out_size) {
    (void)in_sizes; (void)n_in; (void)out_size;
    const float* feat = (const float*)d_in[0];   // (16,256,128,128) f32
    const float* outv = (const float*)d_in[1];   // (16,2,128,128)   f32
    const float* tau  = (const float*)d_in[2];   // scalar f32
    float* outp = (float*)d_out;                 // 8192 f32: fg(4096) ++ bg(4096)

    mask_kernel<<<dim3(BS, MCHUNKS), 256>>>(outv, tau);
    reduce_kernel<<<1, 64>>>();
    topk_kernel<<<dim3(BS, 2), 256>>>(outv, feat);
    sum_kernel<<<dim3(32, BS), 256>>>(feat, outp);
}

// round 11
// speedup vs baseline: 1.6482x; 1.0381x over previous
#include <cuda_runtime.h>
#include <math.h>

// Problem constants (fixed by setup_inputs): bs=16, C=256, H=W=128
#define BS 16
#define CC 256
#define NN 16384           // H*W
#define TOPK 12
#define MCHUNKS 16         // mask kernel chunks per batch
#define QH 4               // row quarters in sum kernel
#define QSZ 4096           // elements per quarter

typedef unsigned long long ull;

// ---------------- scratch (device globals; no allocation allowed) ----------
__device__ __align__(16) float g_fmask_fg[BS][NN];   // 1 MB: fg mask as 0.0/1.0
__device__ __align__(16) float g_fmask_bg[BS][NN];   // 1 MB: bg mask as 0.0/1.0
__device__ int   g_part_cf[BS][MCHUNKS];
__device__ int   g_part_cb[BS][MCHUNKS];
__device__ int   g_part_bad[BS][MCHUNKS];
__device__ float g_fallback[2][BS][CC];              // topk means (written only if cnt==0)
__device__ float g_ptot[QH][BS][CC];                 // per-quarter partial sums
__device__ float g_pfg[QH][BS][CC];
__device__ float g_pbg[QH][BS][CC];

// ---------------- packed f32x2 helpers (ptxas won't auto-fuse) -------------
__device__ __forceinline__ ull add2(ull a, ull b) {
    ull d; asm("add.rn.f32x2 %0, %1, %2;" : "=l"(d) : "l"(a), "l"(b)); return d;
}
__device__ __forceinline__ ull fma2(ull a, ull b, ull c) {
    ull d; asm("fma.rn.f32x2 %0, %1, %2, %3;" : "=l"(d) : "l"(a), "l"(b), "l"(c)); return d;
}
__device__ __forceinline__ float up_sum(ull v) {
    float x, y; asm("mov.b64 {%0, %1}, %2;" : "=f"(x), "=f"(y) : "l"(v)); return x + y;
}

// ---------------------------------------------------------------------------
// Kernel 1: softmax -> float masks (0.0/1.0), per-block partial counts.
// grid = (16, 16) = 256 blocks (full chip), block = 256, one float4/thread.
// ---------------------------------------------------------------------------
__global__ void __launch_bounds__(256) mask_kernel(const float* __restrict__ outp,
                                                   const float* __restrict__ tau_p) {
    const int b  = blockIdx.x;
    const int ch = blockIdx.y;
    const int t  = threadIdx.x;

    const float tau = *tau_p;
    const float Tf  = 1.0f / (1.0f + expf(-tau));   // sigmoid(tau)
    const float Tb  = 1.0f - Tf;

    const int base = ch * 1024;                     // 1024 elements per block
    const float4* o0 = (const float4*)(outp + (size_t)b * (2 * NN) + base);
    const float4* o1 = (const float4*)(outp + (size_t)b * (2 * NN) + NN + base);

    const float4 a  = o0[t];
    const float4 b1 = o1[t];

    float4 mf, mb;
    int cf = 0, cb = 0, bad = 0;
    {
        const float av[4] = {a.x, a.y, a.z, a.w};
        const float bv[4] = {b1.x, b1.y, b1.z, b1.w};
        float rf[4], rb[4];
        #pragma unroll
        for (int k = 0; k < 4; k++) {
            const float m  = fmaxf(av[k], bv[k]);
            const float e0 = expf(av[k] - m);
            const float e1 = expf(bv[k] - m);
            const float s  = e0 + e1;
            const float pf = e1 / s;                // softmax channel 1 (fg)
            const float pb = e0 / s;                // softmax channel 0 (bg)
            const bool ff = pf > Tf;
            const bool fb = pb > Tb;
            rf[k] = ff ? 1.0f : 0.0f;
            rb[k] = fb ? 1.0f : 0.0f;
            cf += ff; cb += fb;
            bad += (ff == fb);
        }
        mf.x = rf[0]; mf.y = rf[1]; mf.z = rf[2]; mf.w = rf[3];
        mb.x = rb[0]; mb.y = rb[1]; mb.z = rb[2]; mb.w = rb[3];
    }
    ((float4*)(&g_fmask_fg[b][base]))[t] = mf;
    ((float4*)(&g_fmask_bg[b][base]))[t] = mb;

    // block reduce partial counts
    #pragma unroll
    for (int o = 16; o > 0; o >>= 1) {
        cf  += __shfl_down_sync(0xffffffffu, cf,  o);
        cb  += __shfl_down_sync(0xffffffffu, cb,  o);
        bad += __shfl_down_sync(0xffffffffu, bad, o);
    }
    __shared__ int rf8[8], rb8[8], rd8[8];
    const int w = t >> 5, l = t & 31;
    if (l == 0) { rf8[w] = cf; rb8[w] = cb; rd8[w] = bad; }
    __syncthreads();
    if (t == 0) {
        int A = 0, B2 = 0, D = 0;
        #pragma unroll
        for (int i = 0; i < 8; i++) { A += rf8[i]; B2 += rb8[i]; D += rd8[i]; }
        g_part_cf[b][ch]  = A;
        g_part_cb[b][ch]  = B2;
        g_part_bad[b][ch] = D;
    }
}

// ---------------------------------------------------------------------------
// Kernel 2: exact top-12 of pred per (b, side); then gather fallback means
// for all 256 channels. Folds its own cnt from partials; early-exits (hot).
// grid = (16, 2), block = 256
// ---------------------------------------------------------------------------
__global__ void __launch_bounds__(256) topk_kernel(const float* __restrict__ outp,
                                                   const float* __restrict__ feat) {
    const int b    = blockIdx.x;
    const int side = blockIdx.y;

    {   // fold count (uniform across block, L2-broadcast)
        int cnt = 0;
        const int* p = (side == 0) ? g_part_cf[b] : g_part_cb[b];
        #pragma unroll
        for (int i = 0; i < MCHUNKS; i++) cnt += p[i];
        if (cnt > 0) return;   // uniform early exit (hot case)
    }

    const int t = threadIdx.x;
    const float* o0 = outp + (size_t)b * (2 * NN);
    const float* o1 = o0 + NN;

    float v[TOPK];
    int   ix[TOPK];
    #pragma unroll
    for (int k = 0; k < TOPK; k++) { v[k] = -INFINITY; ix[k] = 0x7fffffff; }

    for (int j = t; j < NN; j += 256) {
        const float a  = o0[j];
        const float b1 = o1[j];
        const float m  = fmaxf(a, b1);
        const float e0 = expf(a - m);
        const float e1 = expf(b1 - m);
        const float s  = e0 + e1;
        const float p  = (side == 0) ? (e1 / s) : (e0 / s);
        if ((p > v[TOPK - 1]) || (p == v[TOPK - 1] && j < ix[TOPK - 1])) {
            int k = TOPK - 1;
            while (k > 0 && ((p > v[k - 1]) || (p == v[k - 1] && j < ix[k - 1]))) {
                v[k] = v[k - 1]; ix[k] = ix[k - 1]; k--;
            }
            v[k] = p; ix[k] = j;
        }
    }

    __shared__ float sv[256 * TOPK];
    __shared__ int   si[256 * TOPK];
    #pragma unroll
    for (int k = 0; k < TOPK; k++) { sv[t * TOPK + k] = v[k]; si[t * TOPK + k] = ix[k]; }
    __syncthreads();

    for (int stride = 128; stride > 0; stride >>= 1) {
        if (t < stride) {
            float* A  = &sv[t * TOPK];
            int*   Ai = &si[t * TOPK];
            float* B  = &sv[(t + stride) * TOPK];
            int*   Bi = &si[(t + stride) * TOPK];
            float mv[TOPK]; int mi[TOPK];
            int i = 0, j = 0;
            #pragma unroll
            for (int o = 0; o < TOPK; o++) {
                const float av = A[i], bv = B[j];
                const int aix = Ai[i], bix = Bi[j];
                const bool takeA = (av > bv) || (av == bv && aix <= bix);
                if (takeA) { mv[o] = av; mi[o] = aix; i++; }
                else       { mv[o] = bv; mi[o] = bix; j++; }
            }
            #pragma unroll
            for (int o = 0; o < TOPK; o++) { A[o] = mv[o]; Ai[o] = mi[o]; }
        }
        __syncthreads();
    }

    // Gather fallback means for all 256 channels (thread t = channel t)
    const float* rowc = feat + (((size_t)b * CC + t) << 14);
    float s = 0.0f;
    #pragma unroll
    for (int k = 0; k < TOPK; k++) s += rowc[si[k]];
    g_fallback[side][b][t] = s * (1.0f / 12.0f);
}

// ---------------------------------------------------------------------------
// Kernel 3: the 268 MB streaming pass -> per-quarter partial sums.
// grid = (32, 4, 16): cg, quarter h, b. block = 256 (8 warps).
// Warp w owns channel c = cg*8 + w over elements [h*4096, (h+1)*4096).
// 2048 blocks -> fine-grained block scheduling erases the per-SM tail that
// capped R9 at DRAM=71%. fg-mask quarter staged in 16 KB smem, shared by all
// 8 warps. Inner loop: LDG.128 + LDS.128 + 2 ADD.f32x2 + 2 FFMA.f32x2.
// ---------------------------------------------------------------------------
__global__ void __launch_bounds__(256) sum_kernel(const float* __restrict__ feat) {
    __shared__ __align__(16) float s_m[QSZ];   // 16 KB: quarter of one mask row
    __shared__ int s_bad;

    const int t    = threadIdx.x;
    const int w    = t >> 5;
    const int lane = t & 31;
    const int cg   = blockIdx.x;
    const int h    = blockIdx.y;
    const int b    = blockIdx.z;
    const int c    = cg * 8 + w;

    if (t == 0) {
        int d = 0;
        #pragma unroll
        for (int i = 0; i < MCHUNKS; i++) d += g_part_bad[b][i];
        s_bad = d;
    }
    // stage quarter of the fg float-mask row into smem (all 256 threads)
    {
        const float4* src = (const float4*)(&g_fmask_fg[b][h * QSZ]);
        float4*       dst = (float4*)s_m;
        #pragma unroll
        for (int j = 0; j < 4; j++) dst[j * 256 + t] = src[j * 256 + t];
    }
    __syncthreads();
    const bool bad = (s_bad != 0);

    const longlong2* rv  = (const longlong2*)(feat + (((size_t)b * CC + c) << 14) + h * QSZ);
    const longlong2* bv  = (const longlong2*)(&g_fmask_bg[b][h * QSZ]);
    const longlong2* smv = (const longlong2*)s_m;

    ull t2a = 0ull, t2b = 0ull;   // packed running totals
    ull f2a = 0ull, f2b = 0ull;   // packed fg sums
    ull g2a = 0ull, g2b = 0ull;   // packed bg sums (bad path only)

    if (!bad) {
        #pragma unroll 8
        for (int it = 0; it < 32; it++) {
            const longlong2 f = rv[it * 32 + lane];
            const longlong2 m = smv[it * 32 + lane];
            if (it & 1) {
                t2b = add2(t2b, add2((ull)f.x, (ull)f.y));
                f2b = fma2((ull)f.x, (ull)m.x, f2b);
                f2b = fma2((ull)f.y, (ull)m.y, f2b);
            } else {
                t2a = add2(t2a, add2((ull)f.x, (ull)f.y));
                f2a = fma2((ull)f.x, (ull)m.x, f2a);
                f2a = fma2((ull)f.y, (ull)m.y, f2a);
            }
        }
    } else {
        #pragma unroll 4
        for (int it = 0; it < 32; it++) {
            const longlong2 f  = rv[it * 32 + lane];
            const longlong2 m  = smv[it * 32 + lane];
            const longlong2 mb = bv[it * 32 + lane];
            if (it & 1) {
                f2b = fma2((ull)f.x, (ull)m.x,  f2b);
                f2b = fma2((ull)f.y, (ull)m.y,  f2b);
                g2b = fma2((ull)f.x, (ull)mb.x, g2b);
                g2b = fma2((ull)f.y, (ull)mb.y, g2b);
            } else {
                f2a = fma2((ull)f.x, (ull)m.x,  f2a);
                f2a = fma2((ull)f.y, (ull)m.y,  f2a);
                g2a = fma2((ull)f.x, (ull)mb.x, g2a);
                g2a = fma2((ull)f.y, (ull)mb.y, g2a);
            }
        }
    }

    // unpack + warp reduce (one (c, quarter) per warp)
    float tot = up_sum(t2a) + up_sum(t2b);
    float fg  = up_sum(f2a) + up_sum(f2b);
    float bg  = up_sum(g2a) + up_sum(g2b);
    #pragma unroll
    for (int o = 16; o > 0; o >>= 1) {
        tot += __shfl_down_sync(0xffffffffu, tot, o);
        fg  += __shfl_down_sync(0xffffffffu, fg,  o);
        bg  += __shfl_down_sync(0xffffffffu, bg,  o);
    }
    if (lane == 0) {
        g_ptot[h][b][c] = tot;
        g_pfg[h][b][c]  = fg;
        g_pbg[h][b][c]  = bg;
    }
}

// ---------------------------------------------------------------------------
// Kernel 4: fold quarter partials -> output.
// grid = 32 (one block per (side,b)), block = 256 (thread = channel).
// ---------------------------------------------------------------------------
__global__ void __launch_bounds__(256) combine_kernel(float* __restrict__ outp) {
    const int blk  = blockIdx.x;
    const int side = blk >> 4;
    const int b    = blk & 15;
    const int c    = threadIdx.x;

    __shared__ int s_cnt, s_bad;
    if (c == 0) {
        int cnt = 0, bad = 0;
        const int* p = (side == 0) ? g_part_cf[b] : g_part_cb[b];
        #pragma unroll
        for (int i = 0; i < MCHUNKS; i++) { cnt += p[i]; bad += g_part_bad[b][i]; }
        s_cnt = cnt; s_bad = bad;
    }
    __syncthreads();

    float tot = 0.0f, fg = 0.0f, bgp = 0.0f;
    #pragma unroll
    for (int hq = 0; hq < QH; hq++) {
        tot += g_ptot[hq][b][c];
        fg  += g_pfg[hq][b][c];
        bgp += g_pbg[hq][b][c];
    }

    float val;
    if (s_cnt > 0) {
        const float s = (side == 0) ? fg : (s_bad ? bgp : (tot - fg));
        val = s / (float)s_cnt;
    } else {
        val = g_fallback[side][b][c];
    }
    outp[side * 4096 + b * CC + c] = val;
}

// ---------------------------------------------------------------------------
extern "C" void kernel_launch(void* const* d_in, const int* in_sizes, int n_in,
                              void* d_out, int out_size) {
    (void)in_sizes; (void)n_in; (void)out_size;
    const float* feat = (const float*)d_in[0];   // (16,256,128,128) f32
    const float* outv = (const float*)d_in[1];   // (16,2,128,128)   f32
    const float* tau  = (const float*)d_in[2];   // scalar f32
    float* outp = (float*)d_out;                 // 8192 f32: fg(4096) ++ bg(4096)

    mask_kernel<<<dim3(BS, MCHUNKS), 256>>>(outv, tau);
    topk_kernel<<<dim3(BS, 2), 256>>>(outv, feat);
    sum_kernel<<<dim3(32, QH, BS), 256>>>(feat);
    combine_kernel<<<32, 256>>>(outp);
}

// round 12
// speedup vs baseline: 1.6611x; 1.0078x over previous
#include <cuda_runtime.h>
#include <math.h>

// Problem constants (fixed by setup_inputs): bs=16, C=256, H=W=128
#define BS 16
#define CC 256
#define NN 16384           // H*W
#define TOPK 12
#define MCHUNKS 16         // mask kernel chunks per batch
#define QH 4               // row quarters in sum kernel
#define QSZ 4096           // elements per quarter

typedef unsigned long long ull;

// ---------------- scratch (device globals; no allocation allowed) ----------
__device__ __align__(16) float g_fmask_fg[BS][NN];   // 1 MB: fg mask as 0.0/1.0
__device__ __align__(16) float g_fmask_bg[BS][NN];   // 1 MB: bg mask as 0.0/1.0
__device__ int   g_part_cf[BS][MCHUNKS];
__device__ int   g_part_cb[BS][MCHUNKS];
__device__ int   g_part_bad[BS][MCHUNKS];
__device__ float g_fallback[2][BS][CC];              // topk means (written only if cnt==0)
__device__ float g_ptot[QH][BS][CC];                 // per-quarter partial sums
__device__ float g_pfg[QH][BS][CC];
__device__ float g_pbg[QH][BS][CC];

// ---------------- packed f32x2 helpers (ptxas won't auto-fuse) -------------
__device__ __forceinline__ ull add2(ull a, ull b) {
    ull d; asm("add.rn.f32x2 %0, %1, %2;" : "=l"(d) : "l"(a), "l"(b)); return d;
}
__device__ __forceinline__ ull fma2(ull a, ull b, ull c) {
    ull d; asm("fma.rn.f32x2 %0, %1, %2, %3;" : "=l"(d) : "l"(a), "l"(b), "l"(c)); return d;
}
__device__ __forceinline__ float up_sum(ull v) {
    float x, y; asm("mov.b64 {%0, %1}, %2;" : "=f"(x), "=f"(y) : "l"(v)); return x + y;
}

// ---------------------------------------------------------------------------
// Kernel 1: softmax -> float masks (0.0/1.0), per-block partial counts.
// grid = (16, 16) = 256 blocks (full chip), block = 256, one float4/thread.
// ---------------------------------------------------------------------------
__global__ void __launch_bounds__(256) mask_kernel(const float* __restrict__ outp,
                                                   const float* __restrict__ tau_p) {
    const int b  = blockIdx.x;
    const int ch = blockIdx.y;
    const int t  = threadIdx.x;

    const float tau = *tau_p;
    const float Tf  = 1.0f / (1.0f + expf(-tau));   // sigmoid(tau)
    const float Tb  = 1.0f - Tf;

    const int base = ch * 1024;                     // 1024 elements per block
    const float4* o0 = (const float4*)(outp + (size_t)b * (2 * NN) + base);
    const float4* o1 = (const float4*)(outp + (size_t)b * (2 * NN) + NN + base);

    const float4 a  = o0[t];
    const float4 b1 = o1[t];

    float4 mf, mb;
    int cf = 0, cb = 0, bad = 0;
    {
        const float av[4] = {a.x, a.y, a.z, a.w};
        const float bv[4] = {b1.x, b1.y, b1.z, b1.w};
        float rf[4], rb[4];
        #pragma unroll
        for (int k = 0; k < 4; k++) {
            const float m  = fmaxf(av[k], bv[k]);
            const float e0 = expf(av[k] - m);
            const float e1 = expf(bv[k] - m);
            const float s  = e0 + e1;
            const float pf = e1 / s;                // softmax channel 1 (fg)
            const float pb = e0 / s;                // softmax channel 0 (bg)
            const bool ff = pf > Tf;
            const bool fb = pb > Tb;
            rf[k] = ff ? 1.0f : 0.0f;
            rb[k] = fb ? 1.0f : 0.0f;
            cf += ff; cb += fb;
            bad += (ff == fb);
        }
        mf.x = rf[0]; mf.y = rf[1]; mf.z = rf[2]; mf.w = rf[3];
        mb.x = rb[0]; mb.y = rb[1]; mb.z = rb[2]; mb.w = rb[3];
    }
    ((float4*)(&g_fmask_fg[b][base]))[t] = mf;
    ((float4*)(&g_fmask_bg[b][base]))[t] = mb;

    // block reduce partial counts
    #pragma unroll
    for (int o = 16; o > 0; o >>= 1) {
        cf  += __shfl_down_sync(0xffffffffu, cf,  o);
        cb  += __shfl_down_sync(0xffffffffu, cb,  o);
        bad += __shfl_down_sync(0xffffffffu, bad, o);
    }
    __shared__ int rf8[8], rb8[8], rd8[8];
    const int w = t >> 5, l = t & 31;
    if (l == 0) { rf8[w] = cf; rb8[w] = cb; rd8[w] = bad; }
    __syncthreads();
    if (t == 0) {
        int A = 0, B2 = 0, D = 0;
        #pragma unroll
        for (int i = 0; i < 8; i++) { A += rf8[i]; B2 += rb8[i]; D += rd8[i]; }
        g_part_cf[b][ch]  = A;
        g_part_cb[b][ch]  = B2;
        g_part_bad[b][ch] = D;
    }
}

// ---------------------------------------------------------------------------
// Kernel 2: exact top-12 of pred per (b, side); then gather fallback means
// for all 256 channels. Folds its own cnt from partials; early-exits (hot).
// grid = (16, 2), block = 256
// ---------------------------------------------------------------------------
__global__ void __launch_bounds__(256) topk_kernel(const float* __restrict__ outp,
                                                   const float* __restrict__ feat) {
    const int b    = blockIdx.x;
    const int side = blockIdx.y;

    {   // fold count (uniform across block, L2-broadcast)
        int cnt = 0;
        const int* p = (side == 0) ? g_part_cf[b] : g_part_cb[b];
        #pragma unroll
        for (int i = 0; i < MCHUNKS; i++) cnt += p[i];
        if (cnt > 0) return;   // uniform early exit (hot case)
    }

    const int t = threadIdx.x;
    const float* o0 = outp + (size_t)b * (2 * NN);
    const float* o1 = o0 + NN;

    float v[TOPK];
    int   ix[TOPK];
    #pragma unroll
    for (int k = 0; k < TOPK; k++) { v[k] = -INFINITY; ix[k] = 0x7fffffff; }

    for (int j = t; j < NN; j += 256) {
        const float a  = o0[j];
        const float b1 = o1[j];
        const float m  = fmaxf(a, b1);
        const float e0 = expf(a - m);
        const float e1 = expf(b1 - m);
        const float s  = e0 + e1;
        const float p  = (side == 0) ? (e1 / s) : (e0 / s);
        if ((p > v[TOPK - 1]) || (p == v[TOPK - 1] && j < ix[TOPK - 1])) {
            int k = TOPK - 1;
            while (k > 0 && ((p > v[k - 1]) || (p == v[k - 1] && j < ix[k - 1]))) {
                v[k] = v[k - 1]; ix[k] = ix[k - 1]; k--;
            }
            v[k] = p; ix[k] = j;
        }
    }

    __shared__ float sv[256 * TOPK];
    __shared__ int   si[256 * TOPK];
    #pragma unroll
    for (int k = 0; k < TOPK; k++) { sv[t * TOPK + k] = v[k]; si[t * TOPK + k] = ix[k]; }
    __syncthreads();

    for (int stride = 128; stride > 0; stride >>= 1) {
        if (t < stride) {
            float* A  = &sv[t * TOPK];
            int*   Ai = &si[t * TOPK];
            float* B  = &sv[(t + stride) * TOPK];
            int*   Bi = &si[(t + stride) * TOPK];
            float mv[TOPK]; int mi[TOPK];
            int i = 0, j = 0;
            #pragma unroll
            for (int o = 0; o < TOPK; o++) {
                const float av = A[i], bv = B[j];
                const int aix = Ai[i], bix = Bi[j];
                const bool takeA = (av > bv) || (av == bv && aix <= bix);
                if (takeA) { mv[o] = av; mi[o] = aix; i++; }
                else       { mv[o] = bv; mi[o] = bix; j++; }
            }
            #pragma unroll
            for (int o = 0; o < TOPK; o++) { A[o] = mv[o]; Ai[o] = mi[o]; }
        }
        __syncthreads();
    }

    // Gather fallback means for all 256 channels (thread t = channel t)
    const float* rowc = feat + (((size_t)b * CC + t) << 14);
    float s = 0.0f;
    #pragma unroll
    for (int k = 0; k < TOPK; k++) s += rowc[si[k]];
    g_fallback[side][b][t] = s * (1.0f / 12.0f);
}

// ---------------------------------------------------------------------------
// Kernel 3: the 268 MB streaming pass -> per-quarter partial sums.
// grid = (32, 4, 16): cg, quarter h, b. block = 256 (8 warps).
// Warp w owns channel c = cg*8 + w over elements [h*4096, (h+1)*4096).
// 2048 blocks -> fine-grained block scheduling erases the per-SM tail that
// capped R9 at DRAM=71%. fg-mask quarter staged in 16 KB smem, shared by all
// 8 warps. Inner loop: LDG.128 + LDS.128 + 2 ADD.f32x2 + 2 FFMA.f32x2.
// ---------------------------------------------------------------------------
__global__ void __launch_bounds__(256) sum_kernel(const float* __restrict__ feat) {
    __shared__ __align__(16) float s_m[QSZ];   // 16 KB: quarter of one mask row
    __shared__ int s_bad;

    const int t    = threadIdx.x;
    const int w    = t >> 5;
    const int lane = t & 31;
    const int cg   = blockIdx.x;
    const int h    = blockIdx.y;
    const int b    = blockIdx.z;
    const int c    = cg * 8 + w;

    if (t == 0) {
        int d = 0;
        #pragma unroll
        for (int i = 0; i < MCHUNKS; i++) d += g_part_bad[b][i];
        s_bad = d;
    }
    // stage quarter of the fg float-mask row into smem (all 256 threads)
    {
        const float4* src = (const float4*)(&g_fmask_fg[b][h * QSZ]);
        float4*       dst = (float4*)s_m;
        #pragma unroll
        for (int j = 0; j < 4; j++) dst[j * 256 + t] = src[j * 256 + t];
    }
    __syncthreads();
    const bool bad = (s_bad != 0);

    const longlong2* rv  = (const longlong2*)(feat + (((size_t)b * CC + c) << 14) + h * QSZ);
    const longlong2* bv  = (const longlong2*)(&g_fmask_bg[b][h * QSZ]);
    const longlong2* smv = (const longlong2*)s_m;

    ull t2a = 0ull, t2b = 0ull;   // packed running totals
    ull f2a = 0ull, f2b = 0ull;   // packed fg sums
    ull g2a = 0ull, g2b = 0ull;   // packed bg sums (bad path only)

    if (!bad) {
        #pragma unroll 8
        for (int it = 0; it < 32; it++) {
            const longlong2 f = rv[it * 32 + lane];
            const longlong2 m = smv[it * 32 + lane];
            if (it & 1) {
                t2b = add2(t2b, add2((ull)f.x, (ull)f.y));
                f2b = fma2((ull)f.x, (ull)m.x, f2b);
                f2b = fma2((ull)f.y, (ull)m.y, f2b);
            } else {
                t2a = add2(t2a, add2((ull)f.x, (ull)f.y));
                f2a = fma2((ull)f.x, (ull)m.x, f2a);
                f2a = fma2((ull)f.y, (ull)m.y, f2a);
            }
        }
    } else {
        #pragma unroll 4
        for (int it = 0; it < 32; it++) {
            const longlong2 f  = rv[it * 32 + lane];
            const longlong2 m  = smv[it * 32 + lane];
            const longlong2 mb = bv[it * 32 + lane];
            if (it & 1) {
                f2b = fma2((ull)f.x, (ull)m.x,  f2b);
                f2b = fma2((ull)f.y, (ull)m.y,  f2b);
                g2b = fma2((ull)f.x, (ull)mb.x, g2b);
                g2b = fma2((ull)f.y, (ull)mb.y, g2b);
            } else {
                f2a = fma2((ull)f.x, (ull)m.x,  f2a);
                f2a = fma2((ull)f.y, (ull)m.y,  f2a);
                g2a = fma2((ull)f.x, (ull)mb.x, g2a);
                g2a = fma2((ull)f.y, (ull)mb.y, g2a);
            }
        }
    }

    // unpack + warp reduce (one (c, quarter) per warp)
    float tot = up_sum(t2a) + up_sum(t2b);
    float fg  = up_sum(f2a) + up_sum(f2b);
    float bg  = up_sum(g2a) + up_sum(g2b);
    #pragma unroll
    for (int o = 16; o > 0; o >>= 1) {
        tot += __shfl_down_sync(0xffffffffu, tot, o);
        fg  += __shfl_down_sync(0xffffffffu, fg,  o);
        bg  += __shfl_down_sync(0xffffffffu, bg,  o);
    }
    if (lane == 0) {
        g_ptot[h][b][c] = tot;
        g_pfg[h][b][c]  = fg;
        g_pbg[h][b][c]  = bg;
    }
}

// ---------------------------------------------------------------------------
// Kernel 4: fold quarter partials -> output.
// grid = 32 (one block per (side,b)), block = 256 (thread = channel).
// ---------------------------------------------------------------------------
__global__ void __launch_bounds__(256) combine_kernel(float* __restrict__ outp) {
    const int blk  = blockIdx.x;
    const int side = blk >> 4;
    const int b    = blk & 15;
    const int c    = threadIdx.x;

    __shared__ int s_cnt, s_bad;
    if (c == 0) {
        int cnt = 0, bad = 0;
        const int* p = (side == 0) ? g_part_cf[b] : g_part_cb[b];
        #pragma unroll
        for (int i = 0; i < MCHUNKS; i++) { cnt += p[i]; bad += g_part_bad[b][i]; }
        s_cnt = cnt; s_bad = bad;
    }
    __syncthreads();

    float tot = 0.0f, fg = 0.0f, bgp = 0.0f;
    #pragma unroll
    for (int hq = 0; hq < QH; hq++) {
        tot += g_ptot[hq][b][c];
        fg  += g_pfg[hq][b][c];
        bgp += g_pbg[hq][b][c];
    }

    float val;
    if (s_cnt > 0) {
        const float s = (side == 0) ? fg : (s_bad ? bgp : (tot - fg));
        val = s / (float)s_cnt;
    } else {
        val = g_fallback[side][b][c];
    }
    outp[side * 4096 + b * CC + c] = val;
}

// ---------------------------------------------------------------------------
extern "C" void kernel_launch(void* const* d_in, const int* in_sizes, int n_in,
                              void* d_out, int out_size) {
    (void)in_sizes; (void)n_in; (void)out_size;
    const float* feat = (const float*)d_in[0];   // (16,256,128,128) f32
    const float* outv = (const float*)d_in[1];   // (16,2,128,128)   f32
    const float* tau  = (const float*)d_in[2];   // scalar f32
    float* outp = (float*)d_out;                 // 8192 f32: fg(4096) ++ bg(4096)

    mask_kernel<<<dim3(BS, MCHUNKS), 256>>>(outv, tau);
    topk_kernel<<<dim3(BS, 2), 256>>>(outv, feat);
    sum_kernel<<<dim3(32, QH, BS), 256>>>(feat);
    combine_kernel<<<32, 256>>>(outp);
}